// round 10
// baseline (speedup 1.0000x reference)
#include <cuda_runtime.h>
#include <cuda_fp16.h>
#include <cstdint>

// ---------------------------------------------------------------------------
// QGroupLinear: y = x @ (qw*sw)^T + bias   (fp32 in/out)
// mma.sync (HMMA) GEMM, fp16 dequant scratch (rel_err ~3e-4).
// R10: revert to R8 per-chunk barriers; prep MLP=4; merged persistent unit
// loop with cross-unit fragment pre-prime (epilogue overlaps next tile's
// entry) and sched-mbarrier (release/acquire) instead of __syncthreads.
// ---------------------------------------------------------------------------

#define M_TOTAL 4096
#define N_TOTAL 11008
#define K_TOTAL 4096

#define BM 128
#define BN 256
#define STAGES 4
#define KT (K_TOTAL / 64)           // 64 chunks of 64 halfs
#define TILES_M (M_TOTAL / BM)      // 32
#define TILES_N (N_TOTAL / BN)      // 43
#define NTILES (TILES_M * TILES_N)  // 1376
#define NFULL 1368                  // 152 * 9
#define NUNITS (NFULL + (NTILES - NFULL) * 4)   // 1400
#define GRID 152

#define A_BLK_BYTES (BM * 128)      // 16384
#define B_BLK_BYTES (BN * 128)      // 32768
#define STAGE_BYTES (A_BLK_BYTES + B_BLK_BYTES)   // 49152

#define SM_FULL(s)  ((s) * 8)
#define SM_EMPTY(s) (32 + (s) * 8)
#define SM_TILEQ    64
#define SM_SCHED    80
#define SM_DATA     1024
#define SMEM_TOTAL  (SM_DATA + STAGES * STAGE_BYTES)   // 197632

__device__ uint4 d_X16T[2097152];   // 32 MB : block (m_tile*64+kc) = 16 KB
__device__ uint4 d_W16T[5636096];   // 90 MB : block (n_tile*64+kc) = 32 KB
__device__ int   g_tile_ctr;

// ---------------------------------------------------------------------------
__device__ __forceinline__ uint32_t smem_u32(const void* p) {
    uint32_t a;
    asm("{ .reg .u64 t; cvta.to.shared.u64 t, %1; cvt.u32.u64 %0, t; }"
        : "=r"(a) : "l"(p));
    return a;
}

#define MBARRIER_INIT(addr, cnt) \
    asm volatile("mbarrier.init.shared.b64 [%0], %1;" :: "r"((uint32_t)(addr)), "r"((uint32_t)(cnt)) : "memory")
#define MBARRIER_EXPECT_TX(addr, bytes) \
    asm volatile("mbarrier.arrive.expect_tx.shared.b64 _, [%0], %1;" :: "r"((uint32_t)(addr)), "r"((uint32_t)(bytes)) : "memory")
#define MBARRIER_ARRIVE(addr) \
    asm volatile("mbarrier.arrive.shared.b64 _, [%0];" :: "r"((uint32_t)(addr)) : "memory")
#define FENCE_PROXY_ASYNC() asm volatile("fence.proxy.async.shared::cta;" ::: "memory")

#define MBARRIER_WAIT_PARITY(mbar_smem_addr, phase_parity) do { \
    uint32_t _mbar = (uint32_t)(mbar_smem_addr); \
    uint32_t _parity = (uint32_t)(phase_parity); \
    uint32_t _done; \
    asm volatile( \
        "{\n\t.reg .pred p;\n\t" \
        "mbarrier.try_wait.parity.acquire.cta.shared::cta.b64 p, [%1], %2;\n\t" \
        "selp.b32 %0, 1, 0, p;\n\t}" \
        : "=r"(_done) : "r"(_mbar), "r"(_parity) : "memory"); \
    if (!_done) { \
        asm volatile( \
            "{\n\t.reg .pred P1;\n\t" \
            "WAIT_LOOP_%=:\n\t" \
            "mbarrier.try_wait.parity.acquire.cta.shared::cta.b64 P1, [%0], %1, 0x989680;\n\t" \
            "@P1 bra.uni WAIT_DONE_%=;\n\t" \
            "bra.uni WAIT_LOOP_%=;\n\t" \
            "WAIT_DONE_%=:\n\t}" \
            :: "r"(_mbar), "r"(_parity) : "memory"); \
    } \
} while (0)

#define BULK_G2S(dst, src, bytes, mbar) \
    asm volatile("cp.async.bulk.shared::cta.global.mbarrier::complete_tx::bytes [%0], [%1], %2, [%3];" \
        :: "r"((uint32_t)(dst)), "l"((unsigned long long)(src)), "r"((uint32_t)(bytes)), "r"((uint32_t)(mbar)) : "memory")

__device__ __forceinline__ void ldsm4(uint32_t* r, uint32_t addr) {
    asm volatile("ldmatrix.sync.aligned.m8n8.x4.shared.b16 {%0,%1,%2,%3}, [%4];"
                 : "=r"(r[0]), "=r"(r[1]), "=r"(r[2]), "=r"(r[3]) : "r"(addr));
}

__device__ __forceinline__ void mma16816(float* c, const uint32_t* a,
                                         uint32_t b0, uint32_t b1) {
    asm volatile(
        "mma.sync.aligned.m16n8k16.row.col.f32.f16.f16.f32 "
        "{%0,%1,%2,%3}, {%4,%5,%6,%7}, {%8,%9}, {%0,%1,%2,%3};"
        : "+f"(c[0]), "+f"(c[1]), "+f"(c[2]), "+f"(c[3])
        : "r"(a[0]), "r"(a[1]), "r"(a[2]), "r"(a[3]), "r"(b0), "r"(b1));
}

// unit decode: u < NFULL -> full tile; else quarter slice of tiles 1368..1375
__device__ __forceinline__ void decode_unit(int u, int& mt, int& nt, int& nlo) {
    if (u < NFULL) {
        mt = u & (TILES_M - 1); nt = u >> 5; nlo = 0;
    } else {
        int v = u - NFULL;
        int t = NFULL + (v >> 2);
        mt = t & (TILES_M - 1); nt = t >> 5; nlo = (v & 3) * 64;
    }
}

// fill unit-local chunk cloc (R8 protocol: per-chunk expect_tx on full[slot])
__device__ __forceinline__ void fill_chunk(uint32_t sb, int cloc,
                                           const char* aG, const char* bG,
                                           uint32_t bbytes,
                                           int& estage, int& ephase) {
    MBARRIER_WAIT_PARITY(sb + SM_EMPTY(estage), ephase);
    if (++estage == STAGES) { estage = 0; ephase ^= 1; }
    int slot = cloc & 3;
    MBARRIER_EXPECT_TX(sb + SM_FULL(slot), A_BLK_BYTES + bbytes);
    BULK_G2S(sb + SM_DATA + slot * STAGE_BYTES,
             __cvta_generic_to_global(aG + ((size_t)cloc << 14)),
             A_BLK_BYTES, sb + SM_FULL(slot));
    BULK_G2S(sb + SM_DATA + slot * STAGE_BYTES + A_BLK_BYTES,
             __cvta_generic_to_global(bG + ((size_t)cloc << 15)),
             bbytes, sb + SM_FULL(slot));
}

// ---------------------------------------------------------------------------
// Fused prep (MLP=4): each thread converts 16 values (4x16B loads in flight).
// Tiled + SW128-swizzled fp16 blocks; resets tile counter.
// ---------------------------------------------------------------------------
#define XB ((M_TOTAL * K_TOTAL / 16) / 256)    // 4096 blocks
#define WB ((N_TOTAL * K_TOTAL / 16) / 256)    // 11008 blocks

__global__ void __launch_bounds__(256) prep_kernel(const float* __restrict__ x,
                                                   const int* __restrict__ qw,
                                                   const float* __restrict__ sw) {
    if (blockIdx.x == 0 && threadIdx.x == 0) g_tile_ctr = 0;
    int b = blockIdx.x;
    if (b < XB) {
        int idx = b * 256 + threadIdx.x;
        int m = idx >> 8;                      // 256 16-half groups per row
        int k0 = (idx & 255) << 4;
        const float4* src = (const float4*)(x + (size_t)m * K_TOTAL + k0);
        float4 v0 = src[0], v1 = src[1], v2 = src[2], v3 = src[3];
        uint4 p0, p1;
        __half2 h;
        h = __floats2half2_rn(v0.x, v0.y); p0.x = *(uint32_t*)&h;
        h = __floats2half2_rn(v0.z, v0.w); p0.y = *(uint32_t*)&h;
        h = __floats2half2_rn(v1.x, v1.y); p0.z = *(uint32_t*)&h;
        h = __floats2half2_rn(v1.z, v1.w); p0.w = *(uint32_t*)&h;
        h = __floats2half2_rn(v2.x, v2.y); p1.x = *(uint32_t*)&h;
        h = __floats2half2_rn(v2.z, v2.w); p1.y = *(uint32_t*)&h;
        h = __floats2half2_rn(v3.x, v3.y); p1.z = *(uint32_t*)&h;
        h = __floats2half2_rn(v3.z, v3.w); p1.w = *(uint32_t*)&h;
        int blk = (m >> 7) * KT + (k0 >> 6);
        int row = m & 127, ch = k0 & 63;
        uint32_t rb = (uint32_t)row * 128;
        uint32_t sw_ = ((uint32_t)(row & 7)) << 4;
        char* base = (char*)d_X16T + ((size_t)blk << 14);
        *(uint4*)(base + rb + (((uint32_t)ch * 2) ^ sw_)) = p0;
        *(uint4*)(base + rb + (((uint32_t)(ch + 8) * 2) ^ sw_)) = p1;
    } else {
        int idx = (b - XB) * 256 + threadIdx.x;
        int n = idx >> 8;
        int k0 = (idx & 255) << 4;
        const int4* src = (const int4*)(qw + (size_t)n * K_TOTAL + k0);
        int4 q0 = src[0], q1 = src[1], q2 = src[2], q3 = src[3];
        float s = sw[n * 32 + (k0 >> 7)];      // 16 values share one group
        uint4 p0, p1;
        __half2 h;
        h = __floats2half2_rn((float)q0.x * s, (float)q0.y * s); p0.x = *(uint32_t*)&h;
        h = __floats2half2_rn((float)q0.z * s, (float)q0.w * s); p0.y = *(uint32_t*)&h;
        h = __floats2half2_rn((float)q1.x * s, (float)q1.y * s); p0.z = *(uint32_t*)&h;
        h = __floats2half2_rn((float)q1.z * s, (float)q1.w * s); p0.w = *(uint32_t*)&h;
        h = __floats2half2_rn((float)q2.x * s, (float)q2.y * s); p1.x = *(uint32_t*)&h;
        h = __floats2half2_rn((float)q2.z * s, (float)q2.w * s); p1.y = *(uint32_t*)&h;
        h = __floats2half2_rn((float)q3.x * s, (float)q3.y * s); p1.z = *(uint32_t*)&h;
        h = __floats2half2_rn((float)q3.z * s, (float)q3.w * s); p1.w = *(uint32_t*)&h;
        int blk = (n >> 8) * KT + (k0 >> 6);
        int row = n & 255, ch = k0 & 63;
        uint32_t rb = (uint32_t)row * 128;
        uint32_t sw_ = ((uint32_t)(row & 7)) << 4;
        char* base = (char*)d_W16T + ((size_t)blk << 15);
        *(uint4*)(base + rb + (((uint32_t)ch * 2) ^ sw_)) = p0;
        *(uint4*)(base + rb + (((uint32_t)(ch + 8) * 2) ^ sw_)) = p1;
    }
}

// ---------------------------------------------------------------------------
// Per-unit mainloop. NJ = 8 (full 128x256) or 2 (quarter 128x64).
// Fragments (fa/fb) live in the driver so pre-primed values survive across
// unit boundaries. Returns next unit id; sets `primed` if next unit's kk=0
// fragments were pre-loaded during this unit's last k-iteration.
// ---------------------------------------------------------------------------
template <int NJ>
__device__ __forceinline__ int run_unit(uint32_t sb, int tid, int lane, int wid,
                                        int cur_unit, int ti, int* tileq,
                                        int& estage, int& ephase,
                                        int& fstage, int& fphase, int& sphase,
                                        bool& primed,
                                        uint32_t fa[2][4][4], uint32_t fb[2][4][4],
                                        const float* __restrict__ bias,
                                        float* __restrict__ out) {
    int warp_m = wid & 1;
    int warp_n = wid >> 1;
    int m_off = warp_m * 64;
    int n_off = warp_n * (NJ * 8);

    int m_tile, n_tile, n_lo;
    decode_unit(cur_unit, m_tile, n_tile, n_lo);

    const char* aG = (const char*)d_X16T + (((size_t)m_tile * KT) << 14);
    const char* bG = (const char*)d_W16T + (((size_t)n_tile * KT) << 15) + (size_t)n_lo * 128;
    const uint32_t bbytes = NJ * 4096;

    int rowA = m_off + (lane & 15);
    uint32_t xorA = (uint32_t)(rowA & 7) << 4;
    uint32_t cbA = ((uint32_t)(lane >> 4)) << 4;
    uint32_t aRow = sb + SM_DATA + (uint32_t)rowA * 128;

    int rowB = n_off + ((lane & 7) | ((lane & 16) >> 1));
    uint32_t xorB = (uint32_t)(rowB & 7) << 4;
    uint32_t cbB = ((uint32_t)((lane >> 3) & 1)) << 4;
    uint32_t bRow = sb + SM_DATA + A_BLK_BYTES + (uint32_t)rowB * 128;

    float acc[4][NJ][4];
    #pragma unroll
    for (int mi = 0; mi < 4; mi++)
        #pragma unroll
        for (int nj = 0; nj < NJ; nj++)
            #pragma unroll
            for (int r = 0; r < 4; r++) acc[mi][nj][r] = 0.0f;

    auto prefetch = [&](int buf, int s, int kk) {
        uint32_t ka = ((uint32_t)kk * 32 + cbA) ^ xorA;
        uint32_t kb = ((uint32_t)kk * 32 + cbB) ^ xorB;
        uint32_t aS = aRow + (uint32_t)s * STAGE_BYTES + ka;
        uint32_t bS = bRow + (uint32_t)s * STAGE_BYTES + kb;
        #pragma unroll
        for (int mi = 0; mi < 4; mi++)
            ldsm4(fa[buf][mi], aS + mi * (16 * 128));
        #pragma unroll
        for (int nj2 = 0; nj2 < NJ / 2; nj2++)
            ldsm4(fb[buf][nj2], bS + nj2 * (16 * 128));
    };

    if (!primed) prefetch(0, 0, 0);   // chunks 0,1 already full-waited
    bool preprime = false;
    int next_c = -1;                  // consumer view (valid from kt==KT-2)
    int next_p = -1;                  // producer view (tid0)

    for (int kt = 0; kt < KT; kt++) {
        if (tid == 0) {
            if (kt == 0) {
                int t = atomicAdd(&g_tile_ctr, 1);
                next_p = (t < NUNITS) ? t : -1;
                tileq[(ti + 1) & 3] = next_p;
                MBARRIER_ARRIVE(sb + SM_SCHED);   // release -> publishes tileq
            }
            int lt = kt + STAGES - 1;
            if (lt < KT) {
                fill_chunk(sb, lt, aG, bG, bbytes, estage, ephase);
            } else if (next_p >= 0) {
                int nm, nn, nl;
                decode_unit(next_p, nm, nn, nl);
                const char* pa = (const char*)d_X16T + (((size_t)nm * KT) << 14);
                const char* pb = (const char*)d_W16T + (((size_t)nn * KT) << 15) + (size_t)nl * 128;
                uint32_t nb = (next_p < NFULL) ? 32768u : 8192u;
                fill_chunk(sb, lt - KT, pa, pb, nb, estage, ephase);
            }
        }

        int s = kt & (STAGES - 1);
        #pragma unroll
        for (int kk = 0; kk < 4; kk++) {
            int curb = kk & 1, nxtb = curb ^ 1;
            if (kk < 3) {
                prefetch(nxtb, s, kk + 1);
            } else if (kt + 1 < KT) {
                prefetch(nxtb, (kt + 1) & (STAGES - 1), 0);
            } else if (next_c >= 0 && (NJ == 2 || next_c < NFULL)) {
                prefetch(nxtb, 0, 0);         // next unit chunk 0 (same kind)
                preprime = true;
            }
            if (kk == 2) MBARRIER_ARRIVE(sb + SM_EMPTY(s));
            #pragma unroll
            for (int mi = 0; mi < 4; mi++)
                #pragma unroll
                for (int nj = 0; nj < NJ; nj++)
                    mma16816(acc[mi][nj], fa[curb][mi],
                             fb[curb][nj >> 1][(nj & 1) * 2],
                             fb[curb][nj >> 1][(nj & 1) * 2 + 1]);
        }

        if (kt == KT - 2) {                   // learn next unit (acquire)
            MBARRIER_WAIT_PARITY(sb + SM_SCHED, sphase);
            sphase ^= 1;
            next_c = tileq[(ti + 1) & 3];
        }
        // wait chunk kt+2 (may belong to next unit)
        if (kt + 2 < KT || next_c >= 0) {
            MBARRIER_WAIT_PARITY(sb + SM_FULL(fstage), fphase);
            if (++fstage == STAGES) { fstage = 0; fphase ^= 1; }
        }
    }

    // ---- epilogue (next tile's fragments already primed if same-kind) ----
    float* outp = out + (size_t)(m_tile * BM) * N_TOTAL + (size_t)n_tile * BN + n_lo;
    const float* biasp = bias + (size_t)n_tile * BN + n_lo;
    #pragma unroll
    for (int mi = 0; mi < 4; mi++) {
        int r0 = m_off + mi * 16 + (lane >> 2);
        #pragma unroll
        for (int nj = 0; nj < NJ; nj++) {
            int c0 = n_off + nj * 8 + (lane & 3) * 2;
            float2 bv = *(const float2*)(biasp + c0);
            float2 v0, v1;
            v0.x = acc[mi][nj][0] + bv.x;
            v0.y = acc[mi][nj][1] + bv.y;
            v1.x = acc[mi][nj][2] + bv.x;
            v1.y = acc[mi][nj][3] + bv.y;
            *(float2*)(outp + (size_t)r0 * N_TOTAL + c0) = v0;
            *(float2*)(outp + (size_t)(r0 + 8) * N_TOTAL + c0) = v1;
        }
    }

    primed = preprime;
    return next_c;
}

// ---------------------------------------------------------------------------
// Persistent GEMM driver.
// ---------------------------------------------------------------------------
__global__ void __launch_bounds__(256, 1) qgl_gemm_kernel(const float* __restrict__ bias,
                                                          float* __restrict__ out) {
    extern __shared__ char smem[];
    uint32_t sb = smem_u32(smem);
    int tid = threadIdx.x;
    int lane = tid & 31;
    int wid = tid >> 5;

    int* tileq = (int*)(smem + SM_TILEQ);

    if (tid == 0) {
        #pragma unroll
        for (int s = 0; s < STAGES; s++) {
            MBARRIER_INIT(sb + SM_FULL(s), 1);
            MBARRIER_INIT(sb + SM_EMPTY(s), 256);
        }
        MBARRIER_INIT(sb + SM_SCHED, 1);
        FENCE_PROXY_ASYNC();
        int t = atomicAdd(&g_tile_ctr, 1);
        tileq[0] = (t < NUNITS) ? t : -1;
    }
    __syncthreads();

    int estage = 0, ephase = 1;
    int fstage = 0, fphase = 0;
    int sphase = 0;
    int ti = 0;
    int cur = tileq[0];

    uint32_t fa[2][4][4], fb[2][4][4];

    // first-unit prologue: fill chunks 0..2, wait chunks 0,1
    if (tid == 0 && cur >= 0) {
        int mt, nt, nl;
        decode_unit(cur, mt, nt, nl);
        const char* aG = (const char*)d_X16T + (((size_t)mt * KT) << 14);
        const char* bG = (const char*)d_W16T + (((size_t)nt * KT) << 15) + (size_t)nl * 128;
        uint32_t bb = (cur < NFULL) ? 32768u : 8192u;
        #pragma unroll
        for (int s = 0; s < STAGES - 1; s++)
            fill_chunk(sb, s, aG, bG, bb, estage, ephase);
    }
    if (cur >= 0) {
        MBARRIER_WAIT_PARITY(sb + SM_FULL(fstage), fphase);
        if (++fstage == STAGES) { fstage = 0; fphase ^= 1; }
        MBARRIER_WAIT_PARITY(sb + SM_FULL(fstage), fphase);
        if (++fstage == STAGES) { fstage = 0; fphase ^= 1; }
    }

    bool primed = false;
    while (cur >= 0) {
        int nxt;
        if (cur < NFULL)
            nxt = run_unit<8>(sb, tid, lane, wid, cur, ti, tileq,
                              estage, ephase, fstage, fphase, sphase,
                              primed, fa, fb, bias, out);
        else
            nxt = run_unit<2>(sb, tid, lane, wid, cur, ti, tileq,
                              estage, ephase, fstage, fphase, sphase,
                              primed, fa, fb, bias, out);
        ti++;
        cur = nxt;
    }
}

// ---------------------------------------------------------------------------
extern "C" void kernel_launch(void* const* d_in, const int* in_sizes, int n_in,
                              void* d_out, int out_size) {
    const float* x    = (const float*)d_in[0];
    const int*   qw   = (const int*)d_in[1];
    const float* sw   = (const float*)d_in[2];
    const float* bias = (const float*)d_in[3];
    float* out = (float*)d_out;

    prep_kernel<<<XB + WB, 256>>>(x, qw, sw);

    cudaFuncSetAttribute(qgl_gemm_kernel,
                         cudaFuncAttributeMaxDynamicSharedMemorySize, SMEM_TOTAL);
    qgl_gemm_kernel<<<GRID, 256, SMEM_TOTAL>>>(bias, out);
}

// round 11
// speedup vs baseline: 1.0254x; 1.0254x over previous
#include <cuda_runtime.h>
#include <cuda_fp16.h>
#include <cstdint>

// ---------------------------------------------------------------------------
// QGroupLinear: y = x @ (qw*sw)^T + bias   (fp32 in/out)
// mma.sync (HMMA) GEMM, fp16 dequant scratch (rel_err ~3e-4).
// R11: R8 structure (best known) + empty-barrier arrives reduced 256 -> 8
// (lane 0 per warp; single-bank ATOMS serialization was ~10% of tile time)
// + MLP=4 prep.
// ---------------------------------------------------------------------------

#define M_TOTAL 4096
#define N_TOTAL 11008
#define K_TOTAL 4096

#define BM 128
#define BN 256
#define STAGES 4
#define KT (K_TOTAL / 64)           // 64 chunks of 64 halfs
#define TILES_M (M_TOTAL / BM)      // 32
#define TILES_N (N_TOTAL / BN)      // 43
#define NTILES (TILES_M * TILES_N)  // 1376
#define NFULL 1368                  // 152 * 9
#define NUNITS (NFULL + (NTILES - NFULL) * 4)   // 1400
#define GRID 152

#define A_BLK_BYTES (BM * 128)      // 16384
#define B_BLK_BYTES (BN * 128)      // 32768
#define STAGE_BYTES (A_BLK_BYTES + B_BLK_BYTES)   // 49152

#define SM_FULL(s)  ((s) * 8)
#define SM_EMPTY(s) (32 + (s) * 8)
#define SM_TILEQ    64
#define SM_DATA     1024
#define SMEM_TOTAL  (SM_DATA + STAGES * STAGE_BYTES)   // 197632

__device__ uint4 d_X16T[2097152];   // 32 MB : block (m_tile*64+kc) = 16 KB
__device__ uint4 d_W16T[5636096];   // 90 MB : block (n_tile*64+kc) = 32 KB
__device__ int   g_tile_ctr;

// ---------------------------------------------------------------------------
__device__ __forceinline__ uint32_t smem_u32(const void* p) {
    uint32_t a;
    asm("{ .reg .u64 t; cvta.to.shared.u64 t, %1; cvt.u32.u64 %0, t; }"
        : "=r"(a) : "l"(p));
    return a;
}

#define MBARRIER_INIT(addr, cnt) \
    asm volatile("mbarrier.init.shared.b64 [%0], %1;" :: "r"((uint32_t)(addr)), "r"((uint32_t)(cnt)) : "memory")
#define MBARRIER_EXPECT_TX(addr, bytes) \
    asm volatile("mbarrier.arrive.expect_tx.shared.b64 _, [%0], %1;" :: "r"((uint32_t)(addr)), "r"((uint32_t)(bytes)) : "memory")
#define MBARRIER_ARRIVE(addr) \
    asm volatile("mbarrier.arrive.shared.b64 _, [%0];" :: "r"((uint32_t)(addr)) : "memory")
#define FENCE_PROXY_ASYNC() asm volatile("fence.proxy.async.shared::cta;" ::: "memory")

#define MBARRIER_WAIT_PARITY(mbar_smem_addr, phase_parity) do { \
    uint32_t _mbar = (uint32_t)(mbar_smem_addr); \
    uint32_t _parity = (uint32_t)(phase_parity); \
    uint32_t _done; \
    asm volatile( \
        "{\n\t.reg .pred p;\n\t" \
        "mbarrier.try_wait.parity.acquire.cta.shared::cta.b64 p, [%1], %2;\n\t" \
        "selp.b32 %0, 1, 0, p;\n\t}" \
        : "=r"(_done) : "r"(_mbar), "r"(_parity) : "memory"); \
    if (!_done) { \
        asm volatile( \
            "{\n\t.reg .pred P1;\n\t" \
            "WAIT_LOOP_%=:\n\t" \
            "mbarrier.try_wait.parity.acquire.cta.shared::cta.b64 P1, [%0], %1, 0x989680;\n\t" \
            "@P1 bra.uni WAIT_DONE_%=;\n\t" \
            "bra.uni WAIT_LOOP_%=;\n\t" \
            "WAIT_DONE_%=:\n\t}" \
            :: "r"(_mbar), "r"(_parity) : "memory"); \
    } \
} while (0)

#define BULK_G2S(dst, src, bytes, mbar) \
    asm volatile("cp.async.bulk.shared::cta.global.mbarrier::complete_tx::bytes [%0], [%1], %2, [%3];" \
        :: "r"((uint32_t)(dst)), "l"((unsigned long long)(src)), "r"((uint32_t)(bytes)), "r"((uint32_t)(mbar)) : "memory")

__device__ __forceinline__ void ldsm4(uint32_t* r, uint32_t addr) {
    asm volatile("ldmatrix.sync.aligned.m8n8.x4.shared.b16 {%0,%1,%2,%3}, [%4];"
                 : "=r"(r[0]), "=r"(r[1]), "=r"(r[2]), "=r"(r[3]) : "r"(addr));
}

__device__ __forceinline__ void mma16816(float* c, const uint32_t* a,
                                         uint32_t b0, uint32_t b1) {
    asm volatile(
        "mma.sync.aligned.m16n8k16.row.col.f32.f16.f16.f32 "
        "{%0,%1,%2,%3}, {%4,%5,%6,%7}, {%8,%9}, {%0,%1,%2,%3};"
        : "+f"(c[0]), "+f"(c[1]), "+f"(c[2]), "+f"(c[3])
        : "r"(a[0]), "r"(a[1]), "r"(a[2]), "r"(a[3]), "r"(b0), "r"(b1));
}

// unit decode: u < NFULL -> full tile; else quarter slice of tiles 1368..1375
__device__ __forceinline__ void decode_unit(int u, int& mt, int& nt, int& nlo) {
    if (u < NFULL) {
        mt = u & (TILES_M - 1); nt = u >> 5; nlo = 0;
    } else {
        int v = u - NFULL;
        int t = NFULL + (v >> 2);
        mt = t & (TILES_M - 1); nt = t >> 5; nlo = (v & 3) * 64;
    }
}

__device__ __forceinline__ void fill_chunk(uint32_t sb, int cloc,
                                           const char* aG, const char* bG,
                                           uint32_t bbytes,
                                           int& estage, int& ephase) {
    MBARRIER_WAIT_PARITY(sb + SM_EMPTY(estage), ephase);
    if (++estage == STAGES) { estage = 0; ephase ^= 1; }
    int slot = cloc & 3;
    MBARRIER_EXPECT_TX(sb + SM_FULL(slot), A_BLK_BYTES + bbytes);
    BULK_G2S(sb + SM_DATA + slot * STAGE_BYTES,
             __cvta_generic_to_global(aG + ((size_t)cloc << 14)),
             A_BLK_BYTES, sb + SM_FULL(slot));
    BULK_G2S(sb + SM_DATA + slot * STAGE_BYTES + A_BLK_BYTES,
             __cvta_generic_to_global(bG + ((size_t)cloc << 15)),
             bbytes, sb + SM_FULL(slot));
}

// ---------------------------------------------------------------------------
// Fused prep (MLP=4): each thread converts 16 values (4x16B loads in flight).
// ---------------------------------------------------------------------------
#define XB ((M_TOTAL * K_TOTAL / 16) / 256)    // 4096 blocks
#define WB ((N_TOTAL * K_TOTAL / 16) / 256)    // 11008 blocks

__global__ void __launch_bounds__(256) prep_kernel(const float* __restrict__ x,
                                                   const int* __restrict__ qw,
                                                   const float* __restrict__ sw) {
    if (blockIdx.x == 0 && threadIdx.x == 0) g_tile_ctr = 0;
    int b = blockIdx.x;
    if (b < XB) {
        int idx = b * 256 + threadIdx.x;
        int m = idx >> 8;                      // 256 16-half groups per row
        int k0 = (idx & 255) << 4;
        const float4* src = (const float4*)(x + (size_t)m * K_TOTAL + k0);
        float4 v0 = src[0], v1 = src[1], v2 = src[2], v3 = src[3];
        uint4 p0, p1;
        __half2 h;
        h = __floats2half2_rn(v0.x, v0.y); p0.x = *(uint32_t*)&h;
        h = __floats2half2_rn(v0.z, v0.w); p0.y = *(uint32_t*)&h;
        h = __floats2half2_rn(v1.x, v1.y); p0.z = *(uint32_t*)&h;
        h = __floats2half2_rn(v1.z, v1.w); p0.w = *(uint32_t*)&h;
        h = __floats2half2_rn(v2.x, v2.y); p1.x = *(uint32_t*)&h;
        h = __floats2half2_rn(v2.z, v2.w); p1.y = *(uint32_t*)&h;
        h = __floats2half2_rn(v3.x, v3.y); p1.z = *(uint32_t*)&h;
        h = __floats2half2_rn(v3.z, v3.w); p1.w = *(uint32_t*)&h;
        int blk = (m >> 7) * KT + (k0 >> 6);
        int row = m & 127, ch = k0 & 63;
        uint32_t rb = (uint32_t)row * 128;
        uint32_t sw_ = ((uint32_t)(row & 7)) << 4;
        char* base = (char*)d_X16T + ((size_t)blk << 14);
        *(uint4*)(base + rb + (((uint32_t)ch * 2) ^ sw_)) = p0;
        *(uint4*)(base + rb + (((uint32_t)(ch + 8) * 2) ^ sw_)) = p1;
    } else {
        int idx = (b - XB) * 256 + threadIdx.x;
        int n = idx >> 8;
        int k0 = (idx & 255) << 4;
        const int4* src = (const int4*)(qw + (size_t)n * K_TOTAL + k0);
        int4 q0 = src[0], q1 = src[1], q2 = src[2], q3 = src[3];
        float s = sw[n * 32 + (k0 >> 7)];      // 16 values share one group
        uint4 p0, p1;
        __half2 h;
        h = __floats2half2_rn((float)q0.x * s, (float)q0.y * s); p0.x = *(uint32_t*)&h;
        h = __floats2half2_rn((float)q0.z * s, (float)q0.w * s); p0.y = *(uint32_t*)&h;
        h = __floats2half2_rn((float)q1.x * s, (float)q1.y * s); p0.z = *(uint32_t*)&h;
        h = __floats2half2_rn((float)q1.z * s, (float)q1.w * s); p0.w = *(uint32_t*)&h;
        h = __floats2half2_rn((float)q2.x * s, (float)q2.y * s); p1.x = *(uint32_t*)&h;
        h = __floats2half2_rn((float)q2.z * s, (float)q2.w * s); p1.y = *(uint32_t*)&h;
        h = __floats2half2_rn((float)q3.x * s, (float)q3.y * s); p1.z = *(uint32_t*)&h;
        h = __floats2half2_rn((float)q3.z * s, (float)q3.w * s); p1.w = *(uint32_t*)&h;
        int blk = (n >> 8) * KT + (k0 >> 6);
        int row = n & 255, ch = k0 & 63;
        uint32_t rb = (uint32_t)row * 128;
        uint32_t sw_ = ((uint32_t)(row & 7)) << 4;
        char* base = (char*)d_W16T + ((size_t)blk << 15);
        *(uint4*)(base + rb + (((uint32_t)ch * 2) ^ sw_)) = p0;
        *(uint4*)(base + rb + (((uint32_t)(ch + 8) * 2) ^ sw_)) = p1;
    }
}

// ---------------------------------------------------------------------------
// Templated per-unit mainloop. NJ = 8 (full 128x256) or 2 (quarter 128x64).
// Empty barriers: count=8, lane 0 of each warp arrives (warp-collective
// ldmatrix means lane0 program order covers the warp's stage reads).
// ---------------------------------------------------------------------------
template <int NJ>
__device__ __forceinline__ void run_unit(uint32_t sb, int tid, int lane, int wid,
                                         int cur_unit, int ti, int* tileq,
                                         int& estage, int& ephase,
                                         int& fstage, int& fphase,
                                         const float* __restrict__ bias,
                                         float* __restrict__ out) {
    int warp_m = wid & 1;
    int warp_n = wid >> 1;
    int m_off = warp_m * 64;
    int n_off = warp_n * (NJ * 8);

    int m_tile, n_tile, n_lo;
    decode_unit(cur_unit, m_tile, n_tile, n_lo);

    const char* aG = (const char*)d_X16T + (((size_t)m_tile * KT) << 14);
    const char* bG = (const char*)d_W16T + (((size_t)n_tile * KT) << 15) + (size_t)n_lo * 128;
    const uint32_t bbytes = NJ * 4096;

    int rowA = m_off + (lane & 15);
    uint32_t xorA = (uint32_t)(rowA & 7) << 4;
    uint32_t cbA = ((uint32_t)(lane >> 4)) << 4;
    uint32_t aRow = sb + SM_DATA + (uint32_t)rowA * 128;

    int rowB = n_off + ((lane & 7) | ((lane & 16) >> 1));
    uint32_t xorB = (uint32_t)(rowB & 7) << 4;
    uint32_t cbB = ((uint32_t)((lane >> 3) & 1)) << 4;
    uint32_t bRow = sb + SM_DATA + A_BLK_BYTES + (uint32_t)rowB * 128;

    float acc[4][NJ][4];
    #pragma unroll
    for (int mi = 0; mi < 4; mi++)
        #pragma unroll
        for (int nj = 0; nj < NJ; nj++)
            #pragma unroll
            for (int r = 0; r < 4; r++) acc[mi][nj][r] = 0.0f;

    uint32_t fa[2][4][4], fb[2][NJ / 2][4];

    auto prefetch = [&](int buf, int s, int kk) {
        uint32_t ka = ((uint32_t)kk * 32 + cbA) ^ xorA;
        uint32_t kb = ((uint32_t)kk * 32 + cbB) ^ xorB;
        uint32_t aS = aRow + (uint32_t)s * STAGE_BYTES + ka;
        uint32_t bS = bRow + (uint32_t)s * STAGE_BYTES + kb;
        #pragma unroll
        for (int mi = 0; mi < 4; mi++)
            ldsm4(fa[buf][mi], aS + mi * (16 * 128));
        #pragma unroll
        for (int nj2 = 0; nj2 < NJ / 2; nj2++)
            ldsm4(fb[buf][nj2], bS + nj2 * (16 * 128));
    };

    int next_unit = -1;   // tid0 only

    // unit entry: wait chunks 0,1 and prime fragments
    MBARRIER_WAIT_PARITY(sb + SM_FULL(fstage), fphase);
    if (++fstage == STAGES) { fstage = 0; fphase ^= 1; }
    MBARRIER_WAIT_PARITY(sb + SM_FULL(fstage), fphase);
    if (++fstage == STAGES) { fstage = 0; fphase ^= 1; }
    prefetch(0, 0, 0);

    for (int kt = 0; kt < KT; kt++) {
        // ---- producer (tid0): fill chunk kt+3 (may spill into next unit) ----
        if (tid == 0) {
            if (kt == 0) {
                int t = atomicAdd(&g_tile_ctr, 1);
                next_unit = (t < NUNITS) ? t : -1;
                tileq[(ti + 1) & 3] = next_unit;
            }
            int lt = kt + STAGES - 1;
            if (lt < KT) {
                fill_chunk(sb, lt, aG, bG, bbytes, estage, ephase);
            } else if (next_unit >= 0) {
                int nm, nn, nl;
                decode_unit(next_unit, nm, nn, nl);
                const char* pa = (const char*)d_X16T + (((size_t)nm * KT) << 14);
                const char* pb = (const char*)d_W16T + (((size_t)nn * KT) << 15) + (size_t)nl * 128;
                uint32_t nb = (next_unit < NFULL) ? 32768u : 8192u;
                fill_chunk(sb, lt - KT, pa, pb, nb, estage, ephase);
            }
        }

        int s = kt & (STAGES - 1);
        #pragma unroll
        for (int kk = 0; kk < 4; kk++) {
            int curb = kk & 1, nxt = curb ^ 1;
            if (kk < 3)
                prefetch(nxt, s, kk + 1);
            else if (kt + 1 < KT)
                prefetch(nxt, (kt + 1) & (STAGES - 1), 0);
            // last stage-s read was the kk==2 prefetch: lane0-per-warp arrive
            if (kk == 2 && lane == 0) MBARRIER_ARRIVE(sb + SM_EMPTY(s));
            #pragma unroll
            for (int mi = 0; mi < 4; mi++)
                #pragma unroll
                for (int nj = 0; nj < NJ; nj++)
                    mma16816(acc[mi][nj], fa[curb][mi],
                             fb[curb][nj >> 1][(nj & 1) * 2],
                             fb[curb][nj >> 1][(nj & 1) * 2 + 1]);
        }

        // wait chunk kt+2 (needed at iteration kt+1's kk=3 prefetch)
        if (kt + 2 < KT) {
            MBARRIER_WAIT_PARITY(sb + SM_FULL(fstage), fphase);
            if (++fstage == STAGES) { fstage = 0; fphase ^= 1; }
        }
    }

    // ---- epilogue ----
    float* outp = out + (size_t)(m_tile * BM) * N_TOTAL + (size_t)n_tile * BN + n_lo;
    const float* biasp = bias + (size_t)n_tile * BN + n_lo;
    #pragma unroll
    for (int mi = 0; mi < 4; mi++) {
        int r0 = m_off + mi * 16 + (lane >> 2);
        #pragma unroll
        for (int nj = 0; nj < NJ; nj++) {
            int c0 = n_off + nj * 8 + (lane & 3) * 2;
            float2 bv = *(const float2*)(biasp + c0);
            float2 v0, v1;
            v0.x = acc[mi][nj][0] + bv.x;
            v0.y = acc[mi][nj][1] + bv.y;
            v1.x = acc[mi][nj][2] + bv.x;
            v1.y = acc[mi][nj][3] + bv.y;
            *(float2*)(outp + (size_t)r0 * N_TOTAL + c0) = v0;
            *(float2*)(outp + (size_t)(r0 + 8) * N_TOTAL + c0) = v1;
        }
    }
}

// ---------------------------------------------------------------------------
// Persistent GEMM driver.
// ---------------------------------------------------------------------------
__global__ void __launch_bounds__(256, 1) qgl_gemm_kernel(const float* __restrict__ bias,
                                                          float* __restrict__ out) {
    extern __shared__ char smem[];
    uint32_t sb = smem_u32(smem);
    int tid = threadIdx.x;
    int lane = tid & 31;
    int wid = tid >> 5;

    int* tileq = (int*)(smem + SM_TILEQ);

    if (tid == 0) {
        #pragma unroll
        for (int s = 0; s < STAGES; s++) {
            MBARRIER_INIT(sb + SM_FULL(s), 1);
            MBARRIER_INIT(sb + SM_EMPTY(s), 8);     // one arrive per warp
        }
        FENCE_PROXY_ASYNC();
        int t = atomicAdd(&g_tile_ctr, 1);
        tileq[0] = (t < NUNITS) ? t : -1;
    }
    __syncthreads();

    int estage = 0, ephase = 1;
    int fstage = 0, fphase = 0;
    int ti = 0;
    int cur = tileq[0];

    // first-unit prologue: fill chunks 0..2
    if (tid == 0 && cur >= 0) {
        int mt, nt, nl;
        decode_unit(cur, mt, nt, nl);
        const char* aG = (const char*)d_X16T + (((size_t)mt * KT) << 14);
        const char* bG = (const char*)d_W16T + (((size_t)nt * KT) << 15) + (size_t)nl * 128;
        uint32_t bb = (cur < NFULL) ? 32768u : 8192u;
        #pragma unroll
        for (int s = 0; s < STAGES - 1; s++)
            fill_chunk(sb, s, aG, bG, bb, estage, ephase);
    }

    while (cur >= 0) {
        if (cur < NFULL)
            run_unit<8>(sb, tid, lane, wid, cur, ti, tileq,
                        estage, ephase, fstage, fphase, bias, out);
        else
            run_unit<2>(sb, tid, lane, wid, cur, ti, tileq,
                        estage, ephase, fstage, fphase, bias, out);
        ti++;
        __syncthreads();
        cur = tileq[ti & 3];
    }
}

// ---------------------------------------------------------------------------
extern "C" void kernel_launch(void* const* d_in, const int* in_sizes, int n_in,
                              void* d_out, int out_size) {
    const float* x    = (const float*)d_in[0];
    const int*   qw   = (const int*)d_in[1];
    const float* sw   = (const float*)d_in[2];
    const float* bias = (const float*)d_in[3];
    float* out = (float*)d_out;

    prep_kernel<<<XB + WB, 256>>>(x, qw, sw);

    cudaFuncSetAttribute(qgl_gemm_kernel,
                         cudaFuncAttributeMaxDynamicSharedMemorySize, SMEM_TOTAL);
    qgl_gemm_kernel<<<GRID, 256, SMEM_TOTAL>>>(bias, out);
}